// round 3
// baseline (speedup 1.0000x reference)
#include <cuda_runtime.h>

#define Bsz 4096
#define Lsz 512
#define Msz 17
#define Hsz 17
#define Tch 4                       // time-tile (Tch*Msz = 68 floats = 17 float4)
#define NCHUNK (Lsz / Tch)          // 128
#define BLOCK_B 28
#define NTHREADS (BLOCK_B * Hsz)    // 476
#define NBLOCKS ((Bsz + BLOCK_B - 1) / BLOCK_B)  // 147

typedef unsigned long long u64;

__device__ __forceinline__ u64 pk2(float a, float b) {
    u64 r; asm("mov.b64 %0, {%1, %2};" : "=l"(r) : "f"(a), "f"(b)); return r;
}
__device__ __forceinline__ void upk2(u64 v, float &a, float &b) {
    asm("mov.b64 {%0, %1}, %2;" : "=f"(a), "=f"(b) : "l"(v));
}
__device__ __forceinline__ void ffma2(u64 &d, u64 a, u64 b) {
    asm("fma.rn.f32x2 %0, %1, %2, %0;" : "+l"(d) : "l"(a), "l"(b));
}
__device__ __forceinline__ float sigm(float z) {
    return __fdividef(1.0f, 1.0f + __expf(-z));
}
__device__ __forceinline__ float tanh_(float z) {
    return __fdividef(2.0f, 1.0f + __expf(-2.0f * z)) - 1.0f;
}

__global__ __launch_bounds__(NTHREADS, 1) void lstm_scan_kernel(
    const float* __restrict__ x,
    const float* __restrict__ Wih,
    const float* __restrict__ Whh,
    const float* __restrict__ bih,
    const float* __restrict__ bhh,
    float* __restrict__ out)
{
    __shared__ u64 wih_if_s[Msz * Hsz];
    __shared__ u64 wih_go_s[Msz * Hsz];
    __shared__ u64 xs_chunk[BLOCK_B][Tch * Msz];   // staged x, duplicated f32x2
    __shared__ float hbuf[BLOCK_B][Tch * Hsz];     // staged h outputs
    __shared__ u64 hs[2][BLOCK_B][Hsz];            // double-buffered h (dup f32x2)

    const int tid = threadIdx.x;
    const int j = tid % Hsz;      // hidden unit / float4 slot
    const int y = tid / Hsz;      // row within block
    const int b = blockIdx.x * BLOCK_B + y;
    const bool act = (b < Bsz);
    const int bb = act ? b : (Bsz - 1);

    // ---- W_ih into smem, packed (i,f) and (g,o) ----
    if (tid < Msz * Hsz) {
        int k = tid / Hsz, jj = tid % Hsz;
        wih_if_s[tid] = pk2(Wih[jj * Msz + k],             Wih[(Hsz + jj) * Msz + k]);
        wih_go_s[tid] = pk2(Wih[(2 * Hsz + jj) * Msz + k], Wih[(3 * Hsz + jj) * Msz + k]);
    }

    // ---- W_hh in registers, packed ----
    u64 whh_if[Hsz], whh_go[Hsz];
#pragma unroll
    for (int k = 0; k < Hsz; k++) {
        whh_if[k] = pk2(Whh[j * Hsz + k],             Whh[(Hsz + j) * Hsz + k]);
        whh_go[k] = pk2(Whh[(2 * Hsz + j) * Hsz + k], Whh[(3 * Hsz + j) * Hsz + k]);
    }
    const u64 bias_if = pk2(bih[j] + bhh[j],                     bih[Hsz + j] + bhh[Hsz + j]);
    const u64 bias_go = pk2(bih[2 * Hsz + j] + bhh[2 * Hsz + j], bih[3 * Hsz + j] + bhh[3 * Hsz + j]);

    const long OUT_ELEMS = (long)Bsz * Lsz * Hsz;
    const long H_OFF = OUT_ELEMS;
    const long C_OFF = OUT_ELEMS + (long)Bsz * Hsz;
    const long X_OFF = OUT_ELEMS + 2L * (long)Bsz * Hsz;

    const float* xbase   = x   + (long)bb * Lsz * Msz;           // this thread's row
    float*       obase   = out + (long)bb * Lsz * Hsz;
    float*       xobase  = out + X_OFF + (long)bb * Lsz * Msz;

    hs[0][y][j] = 0ULL;
    float c = 0.0f, hn = 0.0f;
    __syncthreads();

    for (int ch = 0; ch < NCHUNK; ch++) {
        const int t0 = ch * Tch;

        // ---- stage x chunk: 1 LDG.128 per thread, mirrored to xout (coalesced) ----
        {
            const float4 v = *((const float4*)(xbase + t0 * Msz) + j);
            if (act) *((float4*)(xobase + t0 * Msz) + j) = v;
            const int base = j * 4;                 // float index within [0,68)
            xs_chunk[y][base + 0] = pk2(v.x, v.x);
            xs_chunk[y][base + 1] = pk2(v.y, v.y);
            xs_chunk[y][base + 2] = pk2(v.z, v.z);
            xs_chunk[y][base + 3] = pk2(v.w, v.w);
        }
        __syncthreads();

#pragma unroll
        for (int tl = 0; tl < Tch; tl++) {
            const int t = t0 + tl;
            const int cur = t & 1, nxt = cur ^ 1;

            u64 aif = bias_if, ago = bias_go;
#pragma unroll
            for (int k = 0; k < Msz; k++) {
                u64 xx = xs_chunk[y][tl * Msz + k];
                ffma2(aif, wih_if_s[k * Hsz + j], xx);
                ffma2(ago, wih_go_s[k * Hsz + j], xx);
            }
#pragma unroll
            for (int k = 0; k < Hsz; k++) {
                u64 hh = hs[cur][y][k];
                ffma2(aif, whh_if[k], hh);
                ffma2(ago, whh_go[k], hh);
            }

            float zi, zf, zg, zo;
            upk2(aif, zi, zf);
            upk2(ago, zg, zo);
            float ig = sigm(zi);
            float fg = sigm(zf);
            float gg = tanh_(zg);
            float og = sigm(zo);
            c  = fg * c + ig * gg;
            hn = og * tanh_(c);

            hbuf[y][tl * Hsz + j] = hn;
            hs[nxt][y][j] = pk2(hn, hn);
            __syncthreads();
        }

        // ---- flush h chunk: LDS.128 + STG.128, coalesced ----
        if (act) {
            const float4 hv = *((const float4*)&hbuf[y][0] + j);
            *((float4*)(obase + t0 * Hsz) + j) = hv;
        }
        // next iteration's staging sync protects hbuf/xs_chunk reuse
    }

    if (act) {
        out[H_OFF + (long)b * Hsz + j] = hn;
        out[C_OFF + (long)b * Hsz + j] = c;
    }
}

extern "C" void kernel_launch(void* const* d_in, const int* in_sizes, int n_in,
                              void* d_out, int out_size) {
    const float* x   = (const float*)d_in[0];
    const float* Wih = (const float*)d_in[1];
    const float* Whh = (const float*)d_in[2];
    const float* bih = (const float*)d_in[3];
    const float* bhh = (const float*)d_in[4];
    float* out = (float*)d_out;
    (void)in_sizes; (void)n_in; (void)out_size;

    lstm_scan_kernel<<<NBLOCKS, NTHREADS>>>(x, Wih, Whh, bih, bhh, out);
}

// round 4
// speedup vs baseline: 1.4070x; 1.4070x over previous
#include <cuda_runtime.h>

#define Bsz 4096
#define Lsz 512
#define Msz 17
#define Hsz 17
#define BL  (Bsz * Lsz)             // 2,097,152 (b,t) rows
#define XW_N (BL * Hsz)             // 35,651,584 float4 entries

#define BLOCK_B 28
#define NTHREADS (BLOCK_B * Hsz)    // 476
#define NBLK2 ((Bsz + BLOCK_B - 1) / BLOCK_B)   // 147
#define NBLK1 148
#define CH_F4 119                   // float4 per 28-row x chunk (28*17/4)
#define NCHUNKS ((BL + BLOCK_B - 1) / BLOCK_B)  // 74899

typedef unsigned long long u64;

// 570 MB scratch: per (b,t,j): (zi0, zf0, zg0, zo0)
__device__ float4 g_xw[XW_N];

__device__ __forceinline__ u64 pk2(float a, float b) {
    u64 r; asm("mov.b64 %0, {%1, %2};" : "=l"(r) : "f"(a), "f"(b)); return r;
}
__device__ __forceinline__ void upk2(u64 v, float &a, float &b) {
    asm("mov.b64 {%0, %1}, %2;" : "=f"(a), "=f"(b) : "l"(v));
}
__device__ __forceinline__ void ffma2(u64 &d, u64 a, u64 b) {
    asm("fma.rn.f32x2 %0, %1, %2, %0;" : "+l"(d) : "l"(a), "l"(b));
}
__device__ __forceinline__ float sigm(float z) {
    return __fdividef(1.0f, 1.0f + __expf(-z));
}
__device__ __forceinline__ float tanh_(float z) {
    return __fdividef(2.0f, 1.0f + __expf(-2.0f * z)) - 1.0f;
}

// ---------------------------------------------------------------------------
// Kernel 1: xw[b,t,:] = x[b,t,:] @ W_ih^T + b_ih + b_hh ; also x passthrough.
// W_ih in per-thread registers; x staged via 1 LDG.128/thread, dup-f32x2 smem.
// ---------------------------------------------------------------------------
__global__ __launch_bounds__(NTHREADS, 1) void proj_kernel(
    const float* __restrict__ x,
    const float* __restrict__ Wih,
    const float* __restrict__ bih,
    const float* __restrict__ bhh,
    float* __restrict__ out)
{
    __shared__ u64 sx[BLOCK_B][20];   // dup x; row stride 160B (16B aligned)

    const int tid = threadIdx.x;
    const int j = tid % Hsz;
    const int y = tid / Hsz;

    // per-thread W_ih pairs for unit j (registers)
    u64 wif[Hsz], wgo[Hsz];
#pragma unroll
    for (int k = 0; k < Hsz; k++) {
        wif[k] = pk2(Wih[j * Msz + k],             Wih[(Hsz + j) * Msz + k]);
        wgo[k] = pk2(Wih[(2 * Hsz + j) * Msz + k], Wih[(3 * Hsz + j) * Msz + k]);
    }
    const u64 b_if = pk2(bih[j] + bhh[j],                     bih[Hsz + j] + bhh[Hsz + j]);
    const u64 b_go = pk2(bih[2 * Hsz + j] + bhh[2 * Hsz + j], bih[3 * Hsz + j] + bhh[3 * Hsz + j]);

    const long X_OFF = (long)BL * Hsz + 2L * Bsz * Hsz;
    float4* xout4 = (float4*)(out + X_OFF);
    const float4* x4 = (const float4*)x;

    const bool stg = (tid < CH_F4);

    // prefetch first chunk
    int ch = blockIdx.x;
    float4 v; bool vok = false;
    if (stg && ch < NCHUNKS) {
        int f4 = ch * CH_F4 + tid;
        if (4 * f4 < BL * Msz) { vok = true; v = x4[f4]; }
    }

    for (; ch < NCHUNKS; ch += NBLK1) {
        // stage chunk ch (held in v), mirror to x passthrough
        if (vok) {
            xout4[ch * CH_F4 + tid] = v;
            float f[4] = {v.x, v.y, v.z, v.w};
            const int fbase = 4 * tid;
#pragma unroll
            for (int i = 0; i < 4; i++) {
                int fi = fbase + i;
                int r = fi / Msz, kk = fi - Msz * r;
                sx[r][kk] = pk2(f[i], f[i]);
            }
        }
        __syncthreads();

        // prefetch next chunk (overlaps with compute)
        {
            int nch = ch + NBLK1;
            vok = false;
            if (stg && nch < NCHUNKS) {
                int f4 = nch * CH_F4 + tid;
                if (4 * f4 < BL * Msz) { vok = true; v = x4[f4]; }
            }
        }

        // compute projections for this chunk
        const int bt = ch * BLOCK_B + y;
        if (bt < BL) {
            u64 aif = b_if, ago = b_go;
            const ulonglong2* rp = (const ulonglong2*)sx[y];
#pragma unroll
            for (int k2 = 0; k2 < 8; k2++) {
                ulonglong2 p = rp[k2];
                ffma2(aif, wif[2 * k2],     p.x);
                ffma2(ago, wgo[2 * k2],     p.x);
                ffma2(aif, wif[2 * k2 + 1], p.y);
                ffma2(ago, wgo[2 * k2 + 1], p.y);
            }
            {
                u64 xl = sx[y][16];
                ffma2(aif, wif[16], xl);
                ffma2(ago, wgo[16], xl);
            }
            float4 o;
            upk2(aif, o.x, o.y);
            upk2(ago, o.z, o.w);
            g_xw[bt * Hsz + j] = o;
        }
        __syncthreads();
    }
}

// ---------------------------------------------------------------------------
// Kernel 2: the recurrence. Per step: 1 LDG.128 (xw, pipelined depth-2),
// 9 LDS (h pairs), 34 FFMA2, activations. W_hh in registers.
// ---------------------------------------------------------------------------
__global__ __launch_bounds__(NTHREADS, 1) void rec_kernel(
    const float* __restrict__ Whh,
    float* __restrict__ out)
{
    __shared__ u64 hsm[2][BLOCK_B][20];        // dup h, double-buffered
    __shared__ float hbuf[BLOCK_B][144];       // 8-step h ring (2 halves of 68)

    const int tid = threadIdx.x;
    const int j = tid % Hsz;
    const int y = tid / Hsz;
    const int b = blockIdx.x * BLOCK_B + y;
    const bool act = (b < Bsz);
    const int bb = act ? b : (Bsz - 1);

    u64 whf[Hsz], wgo[Hsz];
#pragma unroll
    for (int k = 0; k < Hsz; k++) {
        whf[k] = pk2(Whh[j * Hsz + k],             Whh[(Hsz + j) * Hsz + k]);
        wgo[k] = pk2(Whh[(2 * Hsz + j) * Hsz + k], Whh[(3 * Hsz + j) * Hsz + k]);
    }

    const float4* xwrow = g_xw + bb * (Lsz * Hsz) + j;   // step t -> xwrow[t*Hsz]
    float* obase = out + (long)bb * Lsz * Hsz;

    const long OUT_ELEMS = (long)Bsz * Lsz * Hsz;
    const long H_OFF = OUT_ELEMS;
    const long C_OFF = OUT_ELEMS + (long)Bsz * Hsz;

    hsm[0][y][j] = 0ULL;
    float c = 0.0f, hn = 0.0f;

    // depth-2 LDG pipeline
    float4 p0 = xwrow[0];
    float4 p1 = xwrow[Hsz];
    __syncthreads();

    for (int t = 0; t < Lsz; t++) {
        const int cur = t & 1, nxt = cur ^ 1;

        const float4 cv = p0;
        p0 = p1;
        if (t + 2 < Lsz) p1 = xwrow[(t + 2) * Hsz];

        u64 aif = pk2(cv.x, cv.y);
        u64 ago = pk2(cv.z, cv.w);

        const ulonglong2* hp = (const ulonglong2*)hsm[cur][y];
#pragma unroll
        for (int k2 = 0; k2 < 8; k2++) {
            ulonglong2 p = hp[k2];
            ffma2(aif, whf[2 * k2],     p.x);
            ffma2(ago, wgo[2 * k2],     p.x);
            ffma2(aif, whf[2 * k2 + 1], p.y);
            ffma2(ago, wgo[2 * k2 + 1], p.y);
        }
        {
            u64 hh = hsm[cur][y][16];
            ffma2(aif, whf[16], hh);
            ffma2(ago, wgo[16], hh);
        }

        float zi, zf, zg, zo;
        upk2(aif, zi, zf);
        upk2(ago, zg, zo);
        float ig = sigm(zi);
        float fg = sigm(zf);
        float gg = tanh_(zg);
        float og = sigm(zo);
        c  = fg * c + ig * gg;
        hn = og * tanh_(c);

        hbuf[y][(t & 7) * Hsz + j] = hn;       // 8-step ring: safe vs flush
        hsm[nxt][y][j] = pk2(hn, hn);
        __syncthreads();

        if ((t & 3) == 3 && act) {
            const int half = (t >> 2) & 1;     // which 68-float half to flush
            const float4 hv = ((const float4*)&hbuf[y][half * 68])[j];
            ((float4*)(obase + (t - 3) * Hsz))[j] = hv;
        }
    }

    if (act) {
        out[H_OFF + (long)b * Hsz + j] = hn;
        out[C_OFF + (long)b * Hsz + j] = c;
    }
}

extern "C" void kernel_launch(void* const* d_in, const int* in_sizes, int n_in,
                              void* d_out, int out_size) {
    const float* x   = (const float*)d_in[0];
    const float* Wih = (const float*)d_in[1];
    const float* Whh = (const float*)d_in[2];
    const float* bih = (const float*)d_in[3];
    const float* bhh = (const float*)d_in[4];
    float* out = (float*)d_out;
    (void)in_sizes; (void)n_in; (void)out_size;

    proj_kernel<<<NBLK1, NTHREADS>>>(x, Wih, bih, bhh, out);
    rec_kernel<<<NBLK2, NTHREADS>>>(Whh, out);
}

// round 5
// speedup vs baseline: 1.8179x; 1.2920x over previous
#include <cuda_runtime.h>

#define Bsz 4096
#define Lsz 512
#define Msz 17
#define Hsz 17
#define Tch 4
#define NCHUNK (Lsz / Tch)          // 128
#define BLOCK_B 28
#define NTHREADS (BLOCK_B * Hsz)    // 476
#define NBLOCKS ((Bsz + BLOCK_B - 1) / BLOCK_B)  // 147

typedef unsigned long long u64;

__device__ __forceinline__ u64 pk2(float a, float b) {
    u64 r; asm("mov.b64 %0, {%1, %2};" : "=l"(r) : "f"(a), "f"(b)); return r;
}
__device__ __forceinline__ void upk2(u64 v, float &a, float &b) {
    asm("mov.b64 {%0, %1}, %2;" : "=f"(a), "=f"(b) : "l"(v));
}
__device__ __forceinline__ void ffma2(u64 &d, u64 a, u64 b) {
    asm("fma.rn.f32x2 %0, %1, %2, %0;" : "+l"(d) : "l"(a), "l"(b));
}
__device__ __forceinline__ float sigm(float z) {
    return __fdividef(1.0f, 1.0f + __expf(-z));
}
__device__ __forceinline__ float tanh_(float z) {
    return __fdividef(2.0f, 1.0f + __expf(-2.0f * z)) - 1.0f;
}

__global__ __launch_bounds__(NTHREADS, 1) void lstm_fused_kernel(
    const float* __restrict__ x,
    const float* __restrict__ Wih,
    const float* __restrict__ Whh,
    const float* __restrict__ bih,
    const float* __restrict__ bhh,
    float* __restrict__ out)
{
    __shared__ u64 wih_if_s[Msz * Hsz];            // W_ih pairs (i,f), dup not needed (per-j)
    __shared__ u64 wih_go_s[Msz * Hsz];
    __shared__ u64 sx[BLOCK_B][Tch * Msz];         // x chunk, dup f32x2, index k*4 + t
    __shared__ u64 hsm[2][BLOCK_B][20];            // dup h, double-buffered (20 for align)
    __shared__ float hbuf[BLOCK_B][2 * Tch * Hsz]; // 8-step h output ring

    const int tid = threadIdx.x;
    const int j = tid % Hsz;
    const int y = tid / Hsz;
    const int b = blockIdx.x * BLOCK_B + y;
    const bool act = (b < Bsz);
    const int bb = act ? b : (Bsz - 1);

    // ---- W_ih into smem, packed per (k,j) ----
    if (tid < Msz * Hsz) {
        int k = tid / Hsz, jj = tid % Hsz;
        wih_if_s[tid] = pk2(Wih[jj * Msz + k],             Wih[(Hsz + jj) * Msz + k]);
        wih_go_s[tid] = pk2(Wih[(2 * Hsz + jj) * Msz + k], Wih[(3 * Hsz + jj) * Msz + k]);
    }

    // ---- W_hh in registers ----
    u64 whf[Hsz], wgo[Hsz];
#pragma unroll
    for (int k = 0; k < Hsz; k++) {
        whf[k] = pk2(Whh[j * Hsz + k],             Whh[(Hsz + j) * Hsz + k]);
        wgo[k] = pk2(Whh[(2 * Hsz + j) * Hsz + k], Whh[(3 * Hsz + j) * Hsz + k]);
    }
    const u64 b_if = pk2(bih[j] + bhh[j],                     bih[Hsz + j] + bhh[Hsz + j]);
    const u64 b_go = pk2(bih[2 * Hsz + j] + bhh[2 * Hsz + j], bih[3 * Hsz + j] + bhh[3 * Hsz + j]);

    const long OUT_ELEMS = (long)Bsz * Lsz * Hsz;
    const long H_OFF = OUT_ELEMS;
    const long C_OFF = OUT_ELEMS + (long)Bsz * Hsz;
    const long X_OFF = OUT_ELEMS + 2L * (long)Bsz * Hsz;

    const float4* xrow4 = (const float4*)(x + (long)bb * Lsz * Msz);        // chunk ch -> +ch*17
    float4*       xo4   = (float4*)(out + X_OFF + (long)bb * Lsz * Msz);
    float*        obase = out + (long)bb * Lsz * Hsz;

    hsm[0][y][j] = 0ULL;
    float c = 0.0f, hn = 0.0f;

    // prefetch first x chunk (17 float4 per chunk per row; this thread takes slot j)
    float4 v = xrow4[j];

    for (int ch = 0; ch < NCHUNK; ch++) {
        const int t0 = ch * Tch;

        // ---- stage chunk (held in v): mirror to x passthrough + dup into sx ----
        if (act) xo4[ch * Msz + j] = v;
        {
            float f[4] = {v.x, v.y, v.z, v.w};
            const int fbase = 4 * j;               // float index within 68-float chunk
#pragma unroll
            for (int i = 0; i < 4; i++) {
                int fi = fbase + i;
                int t = fi / Msz, k = fi - Msz * t;
                sx[y][k * Tch + t] = pk2(f[i], f[i]);
            }
        }
        // prefetch next chunk early (hide DRAM latency behind this chunk's work)
        if (ch + 1 < NCHUNK) v = xrow4[(ch + 1) * Msz + j];
        __syncthreads();

        // ---- 4-step x-projection burst: weights LDS amortized over 4 timesteps ----
        u64 a_if[Tch], a_go[Tch];
#pragma unroll
        for (int t = 0; t < Tch; t++) { a_if[t] = b_if; a_go[t] = b_go; }
#pragma unroll
        for (int k = 0; k < Msz; k++) {
            const u64 wf = wih_if_s[k * Hsz + j];
            const u64 wg = wih_go_s[k * Hsz + j];
            const ulonglong2 x01 = ((const ulonglong2*)&sx[y][k * Tch])[0];
            const ulonglong2 x23 = ((const ulonglong2*)&sx[y][k * Tch])[1];
            ffma2(a_if[0], wf, x01.x); ffma2(a_go[0], wg, x01.x);
            ffma2(a_if[1], wf, x01.y); ffma2(a_go[1], wg, x01.y);
            ffma2(a_if[2], wf, x23.x); ffma2(a_go[2], wg, x23.x);
            ffma2(a_if[3], wf, x23.y); ffma2(a_go[3], wg, x23.y);
        }

        // ---- 4 recurrence steps ----
#pragma unroll
        for (int tl = 0; tl < Tch; tl++) {
            const int t = t0 + tl;
            const int cur = t & 1, nxt = cur ^ 1;

            u64 aif = a_if[tl], ago = a_go[tl];
            const ulonglong2* hp = (const ulonglong2*)hsm[cur][y];
#pragma unroll
            for (int k2 = 0; k2 < 8; k2++) {
                ulonglong2 p = hp[k2];
                ffma2(aif, whf[2 * k2],     p.x);
                ffma2(ago, wgo[2 * k2],     p.x);
                ffma2(aif, whf[2 * k2 + 1], p.y);
                ffma2(ago, wgo[2 * k2 + 1], p.y);
            }
            {
                u64 hh = hsm[cur][y][16];
                ffma2(aif, whf[16], hh);
                ffma2(ago, wgo[16], hh);
            }

            float zi, zf, zg, zo;
            upk2(aif, zi, zf);
            upk2(ago, zg, zo);
            float ig = sigm(zi);
            float fg = sigm(zf);
            float gg = tanh_(zg);
            float og = sigm(zo);
            c  = fg * c + ig * gg;
            hn = og * tanh_(c);

            hbuf[y][(t & 7) * Hsz + j] = hn;
            hsm[nxt][y][j] = pk2(hn, hn);
            __syncthreads();
        }

        // ---- flush this chunk's h outputs (coalesced float4) ----
        if (act) {
            const int half = ch & 1;               // which 68-float half of the ring
            const float4 hv = ((const float4*)&hbuf[y][half * (Tch * Hsz)])[j];
            ((float4*)(obase + t0 * Hsz))[j] = hv;
        }
        // tl=3 barrier above orders ring writes; next chunk's stage barrier orders sx reuse
    }

    if (act) {
        out[H_OFF + (long)b * Hsz + j] = hn;
        out[C_OFF + (long)b * Hsz + j] = c;
    }
}

extern "C" void kernel_launch(void* const* d_in, const int* in_sizes, int n_in,
                              void* d_out, int out_size) {
    const float* x   = (const float*)d_in[0];
    const float* Wih = (const float*)d_in[1];
    const float* Whh = (const float*)d_in[2];
    const float* bih = (const float*)d_in[3];
    const float* bhh = (const float*)d_in[4];
    float* out = (float*)d_out;
    (void)in_sizes; (void)n_in; (void)out_size;

    lstm_fused_kernel<<<NBLOCKS, NTHREADS>>>(x, Wih, Whh, bih, bhh, out);
}